// round 5
// baseline (speedup 1.0000x reference)
#include <cuda_runtime.h>
#include <math.h>

#define BB 8
#define TT 2560
#define FF 229
#define C1 5
#define C2 11
#define F2 114
#define F3 57
#define FEAT 627
#define OFT 88
#define MCC 48
#define GG 8
#define DH 6
#define KK 31
#define PADW 15
#define TP (TT + 2*PADW)      /* 2590 */
#define KPAD 640
#define NROW (BB*TT)          /* 20480 */
#define BNEPS 1e-5f

// ---- scratch (device globals: allocation-free) ----
__device__ float g_buf1[(long)BB*TT*FF*C1];   // conv1 out, NHWC (b,t,f,c)
__device__ float g_buf2[(long)BB*TT*F2*C1];   // conv2+pool out
__device__ float g_buf3[(long)NROW*FEAT];     // conv3+pool out (c*57+f)
__device__ float g_Wc[3*KPAD*48];             // fused fc+qkv weights, k-major [sec][k][48]
__device__ float g_bc[144];
__device__ float g_q[(long)NROW*MCC];
__device__ float g_k[(long)BB*TP*MCC];        // padded along T
__device__ float g_v[(long)BB*TP*MCC];

// ---- tf32 helpers ----
__device__ __forceinline__ unsigned tf32u(float x) {
    unsigned r; asm("cvt.rna.tf32.f32 %0,%1;" : "=r"(r) : "f"(x)); return r;
}
__device__ __forceinline__ void mma8(float* d, const unsigned* a, const unsigned* b) {
    asm("mma.sync.aligned.m16n8k8.row.col.f32.tf32.tf32.f32 "
        "{%0,%1,%2,%3},{%4,%5,%6,%7},{%8,%9},{%0,%1,%2,%3};"
        : "+f"(d[0]), "+f"(d[1]), "+f"(d[2]), "+f"(d[3])
        : "r"(a[0]), "r"(a[1]), "r"(a[2]), "r"(a[3]), "r"(b[0]), "r"(b[1]));
}

// ------------------------------------------------------------------
// conv1: 1->5 ch, 3x3 SAME, BN, ReLU  (R1 version)
// ------------------------------------------------------------------
__global__ void k_conv1(const float* __restrict__ spec, const float* __restrict__ w,
                        const float* __restrict__ cb, const float* __restrict__ bg,
                        const float* __restrict__ bb, const float* __restrict__ bm,
                        const float* __restrict__ bv) {
    __shared__ float ws[C1*9];
    __shared__ float sA[C1], sD[C1];
    int tid = threadIdx.x;
    if (tid < C1*9) ws[tid] = w[tid];
    if (tid < C1) {
        float s = bg[tid] * rsqrtf(bv[tid] + BNEPS);
        sA[tid] = s;
        sD[tid] = (cb[tid] - bm[tid]) * s + bb[tid];
    }
    __syncthreads();
    long idx = (long)blockIdx.x * blockDim.x + tid;
    if (idx >= (long)BB*TT*FF) return;
    int f = (int)(idx % FF);
    int t = (int)((idx / FF) % TT);
    int b = (int)(idx / ((long)FF*TT));
    float p[3][3];
#pragma unroll
    for (int ky = 0; ky < 3; ky++) {
        int tt2 = t - 1 + ky;
#pragma unroll
        for (int kx = 0; kx < 3; kx++) {
            int ff = f - 1 + kx;
            float val = 0.f;
            if (tt2 >= 0 && tt2 < TT && ff >= 0 && ff < FF)
                val = spec[((long)b*TT + tt2)*FF + ff];
            p[ky][kx] = val;
        }
    }
    float* o = &g_buf1[idx * C1];
#pragma unroll
    for (int c = 0; c < C1; c++) {
        float acc = 0.f;
#pragma unroll
        for (int ky = 0; ky < 3; ky++)
#pragma unroll
            for (int kx = 0; kx < 3; kx++)
                acc = fmaf(ws[c*9 + ky*3 + kx], p[ky][kx], acc);
        o[c] = fmaxf(fmaf(acc, sA[c], sD[c]), 0.f);
    }
}

// ------------------------------------------------------------------
// conv2: 5->5 ch, 3x3 SAME, BN, ReLU, maxpool W (229->114)  (R1 version)
// ------------------------------------------------------------------
__global__ void k_conv2(const float* __restrict__ w, const float* __restrict__ cb,
                        const float* __restrict__ bg, const float* __restrict__ bb,
                        const float* __restrict__ bm, const float* __restrict__ bv) {
    __shared__ float ws[C1*C1*9];
    __shared__ float sA[C1], sD[C1];
    int tid = threadIdx.x;
    for (int i = tid; i < C1*C1*9; i += blockDim.x) ws[i] = w[i];
    if (tid < C1) {
        float s = bg[tid] * rsqrtf(bv[tid] + BNEPS);
        sA[tid] = s;
        sD[tid] = (cb[tid] - bm[tid]) * s + bb[tid];
    }
    __syncthreads();
    long idx = (long)blockIdx.x * blockDim.x + tid;
    if (idx >= (long)BB*TT*F2) return;
    int f2 = (int)(idx % F2);
    int t  = (int)((idx / F2) % TT);
    int b  = (int)(idx / ((long)F2*TT));
    float acc[2][C1];
#pragma unroll
    for (int p = 0; p < 2; p++)
#pragma unroll
        for (int c = 0; c < C1; c++) acc[p][c] = 0.f;

#pragma unroll
    for (int ky = 0; ky < 3; ky++) {
        int tt2 = t - 1 + ky;
        if (tt2 < 0 || tt2 >= TT) continue;
        const float* rowbase = &g_buf1[((long)b*TT + tt2) * FF * C1];
#pragma unroll
        for (int cx = 0; cx < 4; cx++) {
            int ff = 2*f2 - 1 + cx;
            if (ff < 0 || ff >= FF) continue;
            float in5[C1];
            const float* src = rowbase + (long)ff * C1;
#pragma unroll
            for (int ci = 0; ci < C1; ci++) in5[ci] = src[ci];
            if (cx <= 2) {
                int kx = cx;
#pragma unroll
                for (int co = 0; co < C1; co++)
#pragma unroll
                    for (int ci = 0; ci < C1; ci++)
                        acc[0][co] = fmaf(in5[ci], ws[((co*C1+ci)*3+ky)*3+kx], acc[0][co]);
            }
            if (cx >= 1) {
                int kx = cx - 1;
#pragma unroll
                for (int co = 0; co < C1; co++)
#pragma unroll
                    for (int ci = 0; ci < C1; ci++)
                        acc[1][co] = fmaf(in5[ci], ws[((co*C1+ci)*3+ky)*3+kx], acc[1][co]);
            }
        }
    }
    float* o = &g_buf2[idx * C1];
#pragma unroll
    for (int co = 0; co < C1; co++) {
        float y0 = fmaxf(fmaf(acc[0][co], sA[co], sD[co]), 0.f);
        float y1 = fmaxf(fmaf(acc[1][co], sA[co], sD[co]), 0.f);
        o[co] = fmaxf(y0, y1);
    }
}

// ------------------------------------------------------------------
// conv3: 5->11 ch, 3x3 SAME, BN, ReLU, maxpool W (114->57)  (R1 version)
// ------------------------------------------------------------------
__global__ void k_conv3(const float* __restrict__ w, const float* __restrict__ cb,
                        const float* __restrict__ bg, const float* __restrict__ bb,
                        const float* __restrict__ bm, const float* __restrict__ bv) {
    __shared__ float ws[C2*C1*9];
    __shared__ float sA[C2], sD[C2];
    int tid = threadIdx.x;
    for (int i = tid; i < C2*C1*9; i += blockDim.x) ws[i] = w[i];
    if (tid < C2) {
        float s = bg[tid] * rsqrtf(bv[tid] + BNEPS);
        sA[tid] = s;
        sD[tid] = (cb[tid] - bm[tid]) * s + bb[tid];
    }
    __syncthreads();
    long idx = (long)blockIdx.x * blockDim.x + tid;
    if (idx >= (long)BB*TT*F3) return;
    int f2 = (int)(idx % F3);
    int t  = (int)((idx / F3) % TT);
    int b  = (int)(idx / ((long)F3*TT));
    float acc[2][C2];
#pragma unroll
    for (int p = 0; p < 2; p++)
#pragma unroll
        for (int c = 0; c < C2; c++) acc[p][c] = 0.f;

#pragma unroll
    for (int ky = 0; ky < 3; ky++) {
        int tt2 = t - 1 + ky;
        if (tt2 < 0 || tt2 >= TT) continue;
        const float* rowbase = &g_buf2[((long)b*TT + tt2) * F2 * C1];
#pragma unroll
        for (int cx = 0; cx < 4; cx++) {
            int ff = 2*f2 - 1 + cx;
            if (ff < 0 || ff >= F2) continue;
            float in5[C1];
            const float* src = rowbase + (long)ff * C1;
#pragma unroll
            for (int ci = 0; ci < C1; ci++) in5[ci] = src[ci];
            if (cx <= 2) {
                int kx = cx;
#pragma unroll
                for (int co = 0; co < C2; co++)
#pragma unroll
                    for (int ci = 0; ci < C1; ci++)
                        acc[0][co] = fmaf(in5[ci], ws[((co*C1+ci)*3+ky)*3+kx], acc[0][co]);
            }
            if (cx >= 1) {
                int kx = cx - 1;
#pragma unroll
                for (int co = 0; co < C2; co++)
#pragma unroll
                    for (int ci = 0; ci < C1; ci++)
                        acc[1][co] = fmaf(in5[ci], ws[((co*C1+ci)*3+ky)*3+kx], acc[1][co]);
            }
        }
    }
    float* o = &g_buf3[((long)b*TT + t) * FEAT];
#pragma unroll
    for (int co = 0; co < C2; co++) {
        float y0 = fmaxf(fmaf(acc[0][co], sA[co], sD[co]), 0.f);
        float y1 = fmaxf(fmaf(acc[1][co], sA[co], sD[co]), 0.f);
        o[co*F3 + f2] = fmaxf(y0, y1);
    }
}

// ------------------------------------------------------------------
// fold fc into q/k/v, k-major layout: g_Wc[(sec*KPAD + k)*48 + r]
// ------------------------------------------------------------------
__global__ void k_combine(const float* __restrict__ wq, const float* __restrict__ wk,
                          const float* __restrict__ wv, const float* __restrict__ fcw,
                          const float* __restrict__ fcb) {
    int id = blockIdx.x * blockDim.x + threadIdx.x;
    if (id >= 3*KPAD*48) return;
    int r = id % 48;
    int k = (id / 48) % KPAD;
    int sec = id / (KPAD*48);
    const float* wsel = (sec == 0) ? (wq + r*OFT) : (sec == 1) ? (wk + r*OFT) : (wv + r*OFT);
    float acc = 0.f;
    if (k < FEAT) {
        for (int m = 0; m < OFT; m++) acc = fmaf(wsel[m], fcw[(long)m*FEAT + k], acc);
    }
    g_Wc[id] = acc;
    if (k == 0) {
        float bacc = 0.f;
        for (int m = 0; m < OFT; m++) bacc = fmaf(wsel[m], fcb[m], bacc);
        g_bc[sec*48 + r] = bacc;
    }
}

// zero the T-pad rows of k/v
__global__ void k_padzero() {
    int idx = blockIdx.x * blockDim.x + threadIdx.x;
    int total = BB * 2*PADW * MCC;
    if (idx >= total) return;
    int c = idx % MCC;
    int r = (idx / MCC) % (2*PADW);
    int b = idx / (MCC * 2*PADW);
    int tp = (r < PADW) ? r : (TT + PADW + (r - PADW));
    g_k[((long)b*TP + tp)*MCC + c] = 0.f;
    g_v[((long)b*TP + tp)*MCC + c] = 0.f;
}

// ------------------------------------------------------------------
// QKV GEMM on tensor cores: (20480 x 627) @ (627 x 48) per section.
// 3xTF32 error-compensated mma.sync.m16n8k8.
// Block: 256 thr = 8 warps; tile 128 rows x 48 cols; K chunked by 16.
// Warp w: rows [w*16, w*16+16), all 6 n8-tiles.
// ------------------------------------------------------------------
__global__ void __launch_bounds__(256) k_qkv() {
    __shared__ unsigned XsH[128][20];   // stride 20: banks (20r+c)%32 conflict-free for frag pattern
    __shared__ unsigned XsL[128][20];
    __shared__ unsigned WsH[16][56];    // stride 56: 24*kk + col distinct banks
    __shared__ unsigned WsL[16][56];

    int tid = threadIdx.x;
    int sec = blockIdx.y;
    int row0 = blockIdx.x * 128;
    int w = tid >> 5, lane = tid & 31;
    int gid = lane >> 2, tig = lane & 3;
    int R0 = w * 16;

    float acc[6][4];
#pragma unroll
    for (int nt = 0; nt < 6; nt++)
#pragma unroll
        for (int i = 0; i < 4; i++) acc[nt][i] = 0.f;

    for (int k0 = 0; k0 < KPAD; k0 += 16) {
        // stage A tile 128x16, split hi/lo
#pragma unroll
        for (int i = 0; i < 8; i++) {
            int e = tid + 256*i;        // 0..2047
            int r = e >> 4, c = e & 15;
            int kk = k0 + c;
            float x = (kk < FEAT) ? g_buf3[(long)(row0 + r)*FEAT + kk] : 0.f;
            unsigned h = tf32u(x);
            XsH[r][c] = h;
            XsL[r][c] = tf32u(x - __uint_as_float(h));
        }
        // stage B tile 16x48 (g_Wc rows >= FEAT are zero-filled by k_combine)
#pragma unroll
        for (int i = 0; i < 3; i++) {
            int e = tid + 256*i;        // 0..767
            int kk = e / 48, c = e % 48;
            float x = g_Wc[((long)sec*KPAD + k0 + kk)*48 + c];
            unsigned h = tf32u(x);
            WsH[kk][c] = h;
            WsL[kk][c] = tf32u(x - __uint_as_float(h));
        }
        __syncthreads();

#pragma unroll
        for (int k8 = 0; k8 < 16; k8 += 8) {
            unsigned aH[4], aL[4];
            aH[0] = XsH[R0 + gid    ][k8 + tig];
            aH[1] = XsH[R0 + 8 + gid][k8 + tig];
            aH[2] = XsH[R0 + gid    ][k8 + 4 + tig];
            aH[3] = XsH[R0 + 8 + gid][k8 + 4 + tig];
            aL[0] = XsL[R0 + gid    ][k8 + tig];
            aL[1] = XsL[R0 + 8 + gid][k8 + tig];
            aL[2] = XsL[R0 + gid    ][k8 + 4 + tig];
            aL[3] = XsL[R0 + 8 + gid][k8 + 4 + tig];
#pragma unroll
            for (int nt = 0; nt < 6; nt++) {
                unsigned bH[2], bL[2];
                bH[0] = WsH[k8 + tig    ][nt*8 + gid];
                bH[1] = WsH[k8 + 4 + tig][nt*8 + gid];
                bL[0] = WsL[k8 + tig    ][nt*8 + gid];
                bL[1] = WsL[k8 + 4 + tig][nt*8 + gid];
                mma8(acc[nt], aH, bH);
                mma8(acc[nt], aL, bH);
                mma8(acc[nt], aH, bL);
            }
        }
        __syncthreads();
    }

    // writeback with bias
    int rowA = row0 + R0 + gid;
    int rowB = rowA + 8;
    int bA = rowA / TT, tA = rowA % TT;
    int bB = rowB / TT, tB = rowB % TT;
#pragma unroll
    for (int nt = 0; nt < 6; nt++) {
        int col = nt*8 + tig*2;
        float bx = g_bc[sec*48 + col];
        float by = g_bc[sec*48 + col + 1];
        float2 v0 = make_float2(acc[nt][0] + bx, acc[nt][1] + by);
        float2 v1 = make_float2(acc[nt][2] + bx, acc[nt][3] + by);
        if (sec == 0) {
            *(float2*)&g_q[(long)rowA*MCC + col] = v0;
            *(float2*)&g_q[(long)rowB*MCC + col] = v1;
        } else {
            float* dst = (sec == 1) ? g_k : g_v;
            *(float2*)&dst[((long)bA*TP + tA + PADW)*MCC + col] = v0;
            *(float2*)&dst[((long)bB*TP + tB + PADW)*MCC + col] = v1;
        }
    }
}

// ------------------------------------------------------------------
// fused attention + LN + linear + sigmoid; one warp per (b,t)
// ------------------------------------------------------------------
__global__ void k_attn(const float* __restrict__ rel, const float* __restrict__ lng,
                       const float* __restrict__ lnb, const float* __restrict__ linw,
                       const float* __restrict__ linb, float* __restrict__ out) {
    __shared__ float s_rel[MCC*KK];
    __shared__ float s_linw[OFT*MCC];
    __shared__ float s_linb[OFT];
    __shared__ float s_lng[MCC], s_lnb[MCC];
    __shared__ float s_q[8][MCC];
    __shared__ float s_attn[8][GG][KK+1];
    __shared__ float s_h[8][MCC];
    int tid = threadIdx.x;
    for (int i = tid; i < MCC*KK; i += 256) s_rel[i] = rel[i];
    for (int i = tid; i < OFT*MCC; i += 256) s_linw[i] = linw[i];
    if (tid < OFT) s_linb[tid] = linb[tid];
    if (tid < MCC) { s_lng[tid] = lng[tid]; s_lnb[tid] = lnb[tid]; }
    __syncthreads();

    int wid = tid >> 5, lane = tid & 31;
    int bt = blockIdx.x * 8 + wid;
    int b = bt / TT, t = bt % TT;

    s_q[wid][lane] = g_q[(long)bt*MCC + lane];
    if (lane < 16) s_q[wid][lane + 32] = g_q[(long)bt*MCC + lane + 32];
    __syncwarp();

    int j = lane;
    float e[GG];
    if (j < KK) {
        const float* kr = &g_k[((long)b*TP + t + j)*MCC];
#pragma unroll
        for (int g = 0; g < GG; g++) {
            float s = 0.f;
#pragma unroll
            for (int d = 0; d < DH; d++) {
                int c = g*DH + d;
                s = fmaf(s_q[wid][c], kr[c] + s_rel[c*KK + j], s);
            }
            e[g] = s;
        }
    } else {
#pragma unroll
        for (int g = 0; g < GG; g++) e[g] = -INFINITY;
    }

    long aoff = (long)NROW*OFT + (long)bt*GG*KK;
#pragma unroll
    for (int g = 0; g < GG; g++) {
        float m = e[g];
#pragma unroll
        for (int o = 16; o; o >>= 1) m = fmaxf(m, __shfl_xor_sync(0xffffffffu, m, o));
        float p = (j < KK) ? __expf(e[g] - m) : 0.f;
        float s = p;
#pragma unroll
        for (int o = 16; o; o >>= 1) s += __shfl_xor_sync(0xffffffffu, s, o);
        float a = p / s;
        if (j < KK) {
            s_attn[wid][g][j] = a;
            out[aoff + g*KK + j] = a;
        }
    }
    __syncwarp();

    int c1 = lane;
    int c2 = lane + 32;
    int g1 = c1 / DH;
    float o1 = 0.f, o2 = 0.f;
    const float* vbase = &g_v[((long)b*TP + t)*MCC];
#pragma unroll
    for (int jj = 0; jj < KK; jj++) {
        const float* vr = vbase + (long)jj*MCC;
        o1 = fmaf(s_attn[wid][g1][jj], vr[c1], o1);
        if (lane < 16) {
            int g2 = c2 / DH;
            o2 = fmaf(s_attn[wid][g2][jj], vr[c2], o2);
        }
    }

    float lsum = o1 + ((lane < 16) ? o2 : 0.f);
    float lsq  = o1*o1 + ((lane < 16) ? o2*o2 : 0.f);
#pragma unroll
    for (int o = 16; o; o >>= 1) {
        lsum += __shfl_xor_sync(0xffffffffu, lsum, o);
        lsq  += __shfl_xor_sync(0xffffffffu, lsq,  o);
    }
    float mu = lsum * (1.f/48.f);
    float var = lsq * (1.f/48.f) - mu*mu;
    float inv = rsqrtf(var + 1e-5f);
    s_h[wid][c1] = (o1 - mu)*inv*s_lng[c1] + s_lnb[c1];
    if (lane < 16) s_h[wid][c2] = (o2 - mu)*inv*s_lng[c2] + s_lnb[c2];
    __syncwarp();

#pragma unroll
    for (int rr = 0; rr < 3; rr++) {
        int o = lane + rr*32;
        if (o < OFT) {
            float s = s_linb[o];
#pragma unroll
            for (int c = 0; c < MCC; c++)
                s = fmaf(s_h[wid][c], s_linw[o*MCC + c], s);
            out[(long)bt*OFT + o] = 1.f / (1.f + __expf(-s));
        }
    }
}

// ------------------------------------------------------------------
extern "C" void kernel_launch(void* const* d_in, const int* in_sizes, int n_in,
                              void* d_out, int out_size) {
    const float* spec = (const float*)d_in[0];
    const float* c1w  = (const float*)d_in[1];
    const float* c1b  = (const float*)d_in[2];
    const float* bn1g = (const float*)d_in[3];
    const float* bn1b = (const float*)d_in[4];
    const float* bn1m = (const float*)d_in[5];
    const float* bn1v = (const float*)d_in[6];
    const float* c2w  = (const float*)d_in[7];
    const float* c2b  = (const float*)d_in[8];
    const float* bn2g = (const float*)d_in[9];
    const float* bn2b = (const float*)d_in[10];
    const float* bn2m = (const float*)d_in[11];
    const float* bn2v = (const float*)d_in[12];
    const float* c3w  = (const float*)d_in[13];
    const float* c3b  = (const float*)d_in[14];
    const float* bn3g = (const float*)d_in[15];
    const float* bn3b = (const float*)d_in[16];
    const float* bn3m = (const float*)d_in[17];
    const float* bn3v = (const float*)d_in[18];
    const float* fcw  = (const float*)d_in[19];
    const float* fcb  = (const float*)d_in[20];
    const float* wq   = (const float*)d_in[21];
    const float* wk   = (const float*)d_in[22];
    const float* wv   = (const float*)d_in[23];
    const float* rel  = (const float*)d_in[24];
    const float* lng  = (const float*)d_in[25];
    const float* lnb  = (const float*)d_in[26];
    const float* linw = (const float*)d_in[27];
    const float* linb = (const float*)d_in[28];
    float* out = (float*)d_out;

    k_conv1<<<(BB*TT*FF + 255)/256, 256>>>(spec, c1w, c1b, bn1g, bn1b, bn1m, bn1v);
    k_conv2<<<(BB*TT*F2 + 255)/256, 256>>>(c2w, c2b, bn2g, bn2b, bn2m, bn2v);
    k_conv3<<<(BB*TT*F3 + 255)/256, 256>>>(c3w, c3b, bn3g, bn3b, bn3m, bn3v);
    k_combine<<<(3*KPAD*48 + 255)/256, 256>>>(wq, wk, wv, fcw, fcb);
    k_padzero<<<(BB*2*PADW*MCC + 255)/256, 256>>>();
    {
        dim3 grid(NROW/128, 3);
        k_qkv<<<grid, 256>>>();
    }
    k_attn<<<NROW/8, 256>>>(rel, lng, lnb, linw, linb, out);
}

// round 8
// speedup vs baseline: 1.1808x; 1.1808x over previous
#include <cuda_runtime.h>
#include <math.h>

#define BB 8
#define TT 2560
#define FF 229
#define C1 5
#define C2 11
#define F2 114
#define F3 57
#define FEAT 627
#define OFT 88
#define MCC 48
#define GG 8
#define DH 6
#define KK 31
#define PADW 15
#define TP (TT + 2*PADW)      /* 2590 */
#define KPAD 640
#define NROW (BB*TT)          /* 20480 */
#define BNEPS 1e-5f

// ---- scratch (device globals: allocation-free) ----
__device__ float g_buf1[(long)BB*TT*FF*C1];   // conv1 out, NHWC (b,t,f,c)
__device__ float g_buf2[(long)BB*TT*F2*C1];   // conv2+pool out
__device__ float g_buf3[(long)NROW*FEAT];     // conv3+pool out (c*57+f)
__device__ float g_Wc[144*KPAD];              // fused fc+qkv weights (48 q | 48 k | 48 v) x 627 (padded)
__device__ float g_bc[144];
__device__ float g_q[(long)NROW*MCC];
__device__ float g_k[(long)BB*TP*MCC];        // padded along T
__device__ float g_v[(long)BB*TP*MCC];

// ------------------------------------------------------------------
// conv1: 1->5 ch, 3x3 SAME, BN, ReLU
// ------------------------------------------------------------------
__global__ void k_conv1(const float* __restrict__ spec, const float* __restrict__ w,
                        const float* __restrict__ cb, const float* __restrict__ bg,
                        const float* __restrict__ bb, const float* __restrict__ bm,
                        const float* __restrict__ bv) {
    __shared__ float ws[C1*9];
    __shared__ float sA[C1], sD[C1];
    int tid = threadIdx.x;
    if (tid < C1*9) ws[tid] = w[tid];
    if (tid < C1) {
        float s = bg[tid] * rsqrtf(bv[tid] + BNEPS);
        sA[tid] = s;
        sD[tid] = (cb[tid] - bm[tid]) * s + bb[tid];
    }
    __syncthreads();
    long idx = (long)blockIdx.x * blockDim.x + tid;
    if (idx >= (long)BB*TT*FF) return;
    int f = (int)(idx % FF);
    int t = (int)((idx / FF) % TT);
    int b = (int)(idx / ((long)FF*TT));
    float p[3][3];
#pragma unroll
    for (int ky = 0; ky < 3; ky++) {
        int tt2 = t - 1 + ky;
#pragma unroll
        for (int kx = 0; kx < 3; kx++) {
            int ff = f - 1 + kx;
            float val = 0.f;
            if (tt2 >= 0 && tt2 < TT && ff >= 0 && ff < FF)
                val = spec[((long)b*TT + tt2)*FF + ff];
            p[ky][kx] = val;
        }
    }
    float* o = &g_buf1[idx * C1];
#pragma unroll
    for (int c = 0; c < C1; c++) {
        float acc = 0.f;
#pragma unroll
        for (int ky = 0; ky < 3; ky++)
#pragma unroll
            for (int kx = 0; kx < 3; kx++)
                acc = fmaf(ws[c*9 + ky*3 + kx], p[ky][kx], acc);
        o[c] = fmaxf(fmaf(acc, sA[c], sD[c]), 0.f);
    }
}

// ------------------------------------------------------------------
// conv2: 5->5 ch, 3x3 SAME, BN, ReLU, then maxpool W (229->114)
// ------------------------------------------------------------------
__global__ void k_conv2(const float* __restrict__ w, const float* __restrict__ cb,
                        const float* __restrict__ bg, const float* __restrict__ bb,
                        const float* __restrict__ bm, const float* __restrict__ bv) {
    __shared__ float ws[C1*C1*9];
    __shared__ float sA[C1], sD[C1];
    int tid = threadIdx.x;
    for (int i = tid; i < C1*C1*9; i += blockDim.x) ws[i] = w[i];
    if (tid < C1) {
        float s = bg[tid] * rsqrtf(bv[tid] + BNEPS);
        sA[tid] = s;
        sD[tid] = (cb[tid] - bm[tid]) * s + bb[tid];
    }
    __syncthreads();
    long idx = (long)blockIdx.x * blockDim.x + tid;
    if (idx >= (long)BB*TT*F2) return;
    int f2 = (int)(idx % F2);
    int t  = (int)((idx / F2) % TT);
    int b  = (int)(idx / ((long)F2*TT));
    float acc[2][C1];
#pragma unroll
    for (int p = 0; p < 2; p++)
#pragma unroll
        for (int c = 0; c < C1; c++) acc[p][c] = 0.f;

#pragma unroll
    for (int ky = 0; ky < 3; ky++) {
        int tt2 = t - 1 + ky;
        if (tt2 < 0 || tt2 >= TT) continue;
        const float* rowbase = &g_buf1[((long)b*TT + tt2) * FF * C1];
#pragma unroll
        for (int cx = 0; cx < 4; cx++) {
            int ff = 2*f2 - 1 + cx;
            if (ff < 0 || ff >= FF) continue;
            float in5[C1];
            const float* src = rowbase + (long)ff * C1;
#pragma unroll
            for (int ci = 0; ci < C1; ci++) in5[ci] = src[ci];
            if (cx <= 2) {
                int kx = cx;
#pragma unroll
                for (int co = 0; co < C1; co++)
#pragma unroll
                    for (int ci = 0; ci < C1; ci++)
                        acc[0][co] = fmaf(in5[ci], ws[((co*C1+ci)*3+ky)*3+kx], acc[0][co]);
            }
            if (cx >= 1) {
                int kx = cx - 1;
#pragma unroll
                for (int co = 0; co < C1; co++)
#pragma unroll
                    for (int ci = 0; ci < C1; ci++)
                        acc[1][co] = fmaf(in5[ci], ws[((co*C1+ci)*3+ky)*3+kx], acc[1][co]);
            }
        }
    }
    float* o = &g_buf2[idx * C1];
#pragma unroll
    for (int co = 0; co < C1; co++) {
        float y0 = fmaxf(fmaf(acc[0][co], sA[co], sD[co]), 0.f);
        float y1 = fmaxf(fmaf(acc[1][co], sA[co], sD[co]), 0.f);
        o[co] = fmaxf(y0, y1);
    }
}

// ------------------------------------------------------------------
// conv3: 5->11 ch, 3x3 SAME, BN, ReLU, maxpool W (114->57)
// ------------------------------------------------------------------
__global__ void k_conv3(const float* __restrict__ w, const float* __restrict__ cb,
                        const float* __restrict__ bg, const float* __restrict__ bb,
                        const float* __restrict__ bm, const float* __restrict__ bv) {
    __shared__ float ws[C2*C1*9];
    __shared__ float sA[C2], sD[C2];
    int tid = threadIdx.x;
    for (int i = tid; i < C2*C1*9; i += blockDim.x) ws[i] = w[i];
    if (tid < C2) {
        float s = bg[tid] * rsqrtf(bv[tid] + BNEPS);
        sA[tid] = s;
        sD[tid] = (cb[tid] - bm[tid]) * s + bb[tid];
    }
    __syncthreads();
    long idx = (long)blockIdx.x * blockDim.x + tid;
    if (idx >= (long)BB*TT*F3) return;
    int f2 = (int)(idx % F3);
    int t  = (int)((idx / F3) % TT);
    int b  = (int)(idx / ((long)F3*TT));
    float acc[2][C2];
#pragma unroll
    for (int p = 0; p < 2; p++)
#pragma unroll
        for (int c = 0; c < C2; c++) acc[p][c] = 0.f;

#pragma unroll
    for (int ky = 0; ky < 3; ky++) {
        int tt2 = t - 1 + ky;
        if (tt2 < 0 || tt2 >= TT) continue;
        const float* rowbase = &g_buf2[((long)b*TT + tt2) * F2 * C1];
#pragma unroll
        for (int cx = 0; cx < 4; cx++) {
            int ff = 2*f2 - 1 + cx;
            if (ff < 0 || ff >= F2) continue;
            float in5[C1];
            const float* src = rowbase + (long)ff * C1;
#pragma unroll
            for (int ci = 0; ci < C1; ci++) in5[ci] = src[ci];
            if (cx <= 2) {
                int kx = cx;
#pragma unroll
                for (int co = 0; co < C2; co++)
#pragma unroll
                    for (int ci = 0; ci < C1; ci++)
                        acc[0][co] = fmaf(in5[ci], ws[((co*C1+ci)*3+ky)*3+kx], acc[0][co]);
            }
            if (cx >= 1) {
                int kx = cx - 1;
#pragma unroll
                for (int co = 0; co < C2; co++)
#pragma unroll
                    for (int ci = 0; ci < C1; ci++)
                        acc[1][co] = fmaf(in5[ci], ws[((co*C1+ci)*3+ky)*3+kx], acc[1][co]);
            }
        }
    }
    float* o = &g_buf3[((long)b*TT + t) * FEAT];
#pragma unroll
    for (int co = 0; co < C2; co++) {
        float y0 = fmaxf(fmaf(acc[0][co], sA[co], sD[co]), 0.f);
        float y1 = fmaxf(fmaf(acc[1][co], sA[co], sD[co]), 0.f);
        o[co*F3 + f2] = fmaxf(y0, y1);
    }
}

// ------------------------------------------------------------------
// fold fc into q/k/v (R1 layout: g_Wc[r*KPAD + k], r = sec*48 + col)
// ------------------------------------------------------------------
__global__ void k_combine(const float* __restrict__ wq, const float* __restrict__ wk,
                          const float* __restrict__ wv, const float* __restrict__ fcw,
                          const float* __restrict__ fcb) {
    int idx = blockIdx.x * blockDim.x + threadIdx.x;
    if (idx >= 144*KPAD) return;
    int r = idx / KPAD, k = idx % KPAD;
    const float* wsel = (r < 48) ? (wq + r*OFT) : (r < 96) ? (wk + (r-48)*OFT) : (wv + (r-96)*OFT);
    float acc = 0.f;
    if (k < FEAT) {
        for (int m = 0; m < OFT; m++) acc = fmaf(wsel[m], fcw[(long)m*FEAT + k], acc);
    }
    g_Wc[idx] = acc;
    if (k == 0) {
        float bacc = 0.f;
        for (int m = 0; m < OFT; m++) bacc = fmaf(wsel[m], fcb[m], bacc);
        g_bc[r] = bacc;
    }
}

// zero the T-pad rows of k/v
__global__ void k_padzero() {
    int idx = blockIdx.x * blockDim.x + threadIdx.x;
    int total = BB * 2*PADW * MCC;
    if (idx >= total) return;
    int c = idx % MCC;
    int r = (idx / MCC) % (2*PADW);
    int b = idx / (MCC * 2*PADW);
    int tp = (r < PADW) ? r : (TT + PADW + (r - PADW));
    g_k[((long)b*TP + tp)*MCC + c] = 0.f;
    g_v[((long)b*TP + tp)*MCC + c] = 0.f;
}

// ------------------------------------------------------------------
// QKV GEMM v2: (20480 x 627) @ (627 x 48) per section (q,k,v via blockIdx.y)
// 128x48 tile per block, 256 threads, 4x6 microtile.
// B tile transposed in smem (k-major rows, stride 50 => 8B aligned) so
// the 6 B operands per k-step come from 3x LDS.64.
// Inner loop: 4 LDS.32 + 3 LDS.64 + 24 FFMA = 31 issues / 24 MACs.
// ------------------------------------------------------------------
__global__ void __launch_bounds__(256) k_qkv() {
    __shared__ float Xs[128][33];
    __shared__ float Ws[32][50];
    int tid = threadIdx.x;
    int sec = blockIdx.y;
    int row0 = blockIdx.x * 128;
    int tx = tid & 7;      // col group: cols [tx*6, tx*6+6)
    int ty = tid >> 3;     // row group: rows [ty*4, ty*4+4)

    float bias[6];
#pragma unroll
    for (int j = 0; j < 6; j++) bias[j] = g_bc[sec*48 + tx*6 + j];

    float acc[4][6];
#pragma unroll
    for (int i = 0; i < 4; i++)
#pragma unroll
        for (int j = 0; j < 6; j++) acc[i][j] = 0.f;

    for (int k0 = 0; k0 < KPAD; k0 += 32) {
        // stage X tile 128x32 (coalesced loads, conflict-free stores)
#pragma unroll
        for (int i = 0; i < 16; i++) {
            int e = tid + 256*i;
            int r = e >> 5, c = e & 31;
            int kk = k0 + c;
            Xs[r][c] = (kk < FEAT) ? g_buf3[(long)(row0 + r)*FEAT + kk] : 0.f;
        }
        // stage W tile 48x32, transposed into Ws[k][col]
#pragma unroll
        for (int i = 0; i < 6; i++) {
            int e = tid + 256*i;
            int r = e >> 5, c = e & 31;   // r: output col 0..47, c: k offset 0..31
            Ws[c][r] = g_Wc[(long)(sec*48 + r)*KPAD + k0 + c];
        }
        __syncthreads();

#pragma unroll
        for (int kk = 0; kk < 32; kk++) {
            float2 b01 = *(const float2*)&Ws[kk][tx*6];
            float2 b23 = *(const float2*)&Ws[kk][tx*6 + 2];
            float2 b45 = *(const float2*)&Ws[kk][tx*6 + 4];
            float bv[6] = {b01.x, b01.y, b23.x, b23.y, b45.x, b45.y};
#pragma unroll
            for (int i = 0; i < 4; i++) {
                float a = Xs[ty*4 + i][kk];
#pragma unroll
                for (int j = 0; j < 6; j++)
                    acc[i][j] = fmaf(a, bv[j], acc[i][j]);
            }
        }
        __syncthreads();
    }

    // writeback with bias
#pragma unroll
    for (int i = 0; i < 4; i++) {
        int row = row0 + ty*4 + i;
        int b = row / TT, t = row % TT;
        float2 v0 = make_float2(acc[i][0] + bias[0], acc[i][1] + bias[1]);
        float2 v1 = make_float2(acc[i][2] + bias[2], acc[i][3] + bias[3]);
        float2 v2 = make_float2(acc[i][4] + bias[4], acc[i][5] + bias[5]);
        if (sec == 0) {
            float* dst = &g_q[(long)row*MCC + tx*6];
            *(float2*)(dst)     = v0;
            *(float2*)(dst + 2) = v1;
            *(float2*)(dst + 4) = v2;
        } else {
            float* base = (sec == 1) ? g_k : g_v;
            float* dst = &base[((long)b*TP + t + PADW)*MCC + tx*6];
            *(float2*)(dst)     = v0;
            *(float2*)(dst + 2) = v1;
            *(float2*)(dst + 4) = v2;
        }
    }
}

// ------------------------------------------------------------------
// fused attention + LN + linear + sigmoid; one warp per (b,t)
// ------------------------------------------------------------------
__global__ void k_attn(const float* __restrict__ rel, const float* __restrict__ lng,
                       const float* __restrict__ lnb, const float* __restrict__ linw,
                       const float* __restrict__ linb, float* __restrict__ out) {
    __shared__ float s_rel[MCC*KK];
    __shared__ float s_linw[OFT*MCC];
    __shared__ float s_linb[OFT];
    __shared__ float s_lng[MCC], s_lnb[MCC];
    __shared__ float s_q[8][MCC];
    __shared__ float s_attn[8][GG][KK+1];
    __shared__ float s_h[8][MCC];
    int tid = threadIdx.x;
    for (int i = tid; i < MCC*KK; i += 256) s_rel[i] = rel[i];
    for (int i = tid; i < OFT*MCC; i += 256) s_linw[i] = linw[i];
    if (tid < OFT) s_linb[tid] = linb[tid];
    if (tid < MCC) { s_lng[tid] = lng[tid]; s_lnb[tid] = lnb[tid]; }
    __syncthreads();

    int wid = tid >> 5, lane = tid & 31;
    int bt = blockIdx.x * 8 + wid;
    int b = bt / TT, t = bt % TT;

    s_q[wid][lane] = g_q[(long)bt*MCC + lane];
    if (lane < 16) s_q[wid][lane + 32] = g_q[(long)bt*MCC + lane + 32];
    __syncwarp();

    int j = lane;
    float e[GG];
    if (j < KK) {
        const float* kr = &g_k[((long)b*TP + t + j)*MCC];
#pragma unroll
        for (int g = 0; g < GG; g++) {
            float s = 0.f;
#pragma unroll
            for (int d = 0; d < DH; d++) {
                int c = g*DH + d;
                s = fmaf(s_q[wid][c], kr[c] + s_rel[c*KK + j], s);
            }
            e[g] = s;
        }
    } else {
#pragma unroll
        for (int g = 0; g < GG; g++) e[g] = -INFINITY;
    }

    long aoff = (long)NROW*OFT + (long)bt*GG*KK;
#pragma unroll
    for (int g = 0; g < GG; g++) {
        float m = e[g];
#pragma unroll
        for (int o = 16; o; o >>= 1) m = fmaxf(m, __shfl_xor_sync(0xffffffffu, m, o));
        float p = (j < KK) ? __expf(e[g] - m) : 0.f;
        float s = p;
#pragma unroll
        for (int o = 16; o; o >>= 1) s += __shfl_xor_sync(0xffffffffu, s, o);
        float a = p / s;
        if (j < KK) {
            s_attn[wid][g][j] = a;
            out[aoff + g*KK + j] = a;
        }
    }
    __syncwarp();

    int c1 = lane;
    int c2 = lane + 32;
    int g1 = c1 / DH;
    float o1 = 0.f, o2 = 0.f;
    const float* vbase = &g_v[((long)b*TP + t)*MCC];
#pragma unroll
    for (int jj = 0; jj < KK; jj++) {
        const float* vr = vbase + (long)jj*MCC;
        o1 = fmaf(s_attn[wid][g1][jj], vr[c1], o1);
        if (lane < 16) {
            int g2 = c2 / DH;
            o2 = fmaf(s_attn[wid][g2][jj], vr[c2], o2);
        }
    }

    float lsum = o1 + ((lane < 16) ? o2 : 0.f);
    float lsq  = o1*o1 + ((lane < 16) ? o2*o2 : 0.f);
#pragma unroll
    for (int o = 16; o; o >>= 1) {
        lsum += __shfl_xor_sync(0xffffffffu, lsum, o);
        lsq  += __shfl_xor_sync(0xffffffffu, lsq,  o);
    }
    float mu = lsum * (1.f/48.f);
    float var = lsq * (1.f/48.f) - mu*mu;
    float inv = rsqrtf(var + 1e-5f);
    s_h[wid][c1] = (o1 - mu)*inv*s_lng[c1] + s_lnb[c1];
    if (lane < 16) s_h[wid][c2] = (o2 - mu)*inv*s_lng[c2] + s_lnb[c2];
    __syncwarp();

#pragma unroll
    for (int rr = 0; rr < 3; rr++) {
        int o = lane + rr*32;
        if (o < OFT) {
            float s = s_linb[o];
#pragma unroll
            for (int c = 0; c < MCC; c++)
                s = fmaf(s_h[wid][c], s_linw[o*MCC + c], s);
            out[(long)bt*OFT + o] = 1.f / (1.f + __expf(-s));
        }
    }
}

// ------------------------------------------------------------------
extern "C" void kernel_launch(void* const* d_in, const int* in_sizes, int n_in,
                              void* d_out, int out_size) {
    const float* spec = (const float*)d_in[0];
    const float* c1w  = (const float*)d_in[1];
    const float* c1b  = (const float*)d_in[2];
    const float* bn1g = (const float*)d_in[3];
    const float* bn1b = (const float*)d_in[4];
    const float* bn1m = (const float*)d_in[5];
    const float* bn1v = (const float*)d_in[6];
    const float* c2w  = (const float*)d_in[7];
    const float* c2b  = (const float*)d_in[8];
    const float* bn2g = (const float*)d_in[9];
    const float* bn2b = (const float*)d_in[10];
    const float* bn2m = (const float*)d_in[11];
    const float* bn2v = (const float*)d_in[12];
    const float* c3w  = (const float*)d_in[13];
    const float* c3b  = (const float*)d_in[14];
    const float* bn3g = (const float*)d_in[15];
    const float* bn3b = (const float*)d_in[16];
    const float* bn3m = (const float*)d_in[17];
    const float* bn3v = (const float*)d_in[18];
    const float* fcw  = (const float*)d_in[19];
    const float* fcb  = (const float*)d_in[20];
    const float* wq   = (const float*)d_in[21];
    const float* wk   = (const float*)d_in[22];
    const float* wv   = (const float*)d_in[23];
    const float* rel  = (const float*)d_in[24];
    const float* lng  = (const float*)d_in[25];
    const float* lnb  = (const float*)d_in[26];
    const float* linw = (const float*)d_in[27];
    const float* linb = (const float*)d_in[28];
    float* out = (float*)d_out;

    k_conv1<<<(BB*TT*FF + 255)/256, 256>>>(spec, c1w, c1b, bn1g, bn1b, bn1m, bn1v);
    k_conv2<<<(BB*TT*F2 + 255)/256, 256>>>(c2w, c2b, bn2g, bn2b, bn2m, bn2v);
    k_conv3<<<(BB*TT*F3 + 255)/256, 256>>>(c3w, c3b, bn3g, bn3b, bn3m, bn3v);
    k_combine<<<(144*KPAD + 255)/256, 256>>>(wq, wk, wv, fcw, fcb);
    k_padzero<<<(BB*2*PADW*MCC + 255)/256, 256>>>();
    {
        dim3 grid(NROW/128, 3);
        k_qkv<<<grid, 256>>>();
    }
    k_attn<<<NROW/8, 256>>>(rel, lng, lnb, linw, linb, out);
}

// round 17
// speedup vs baseline: 1.4316x; 1.2123x over previous
#include <cuda_runtime.h>
#include <math.h>

#define BB 8
#define TT 2560
#define FF 229
#define C1 5
#define C2 11
#define F2 114
#define F3 57
#define FEAT 627
#define OFT 88
#define MCC 48
#define GG 8
#define DH 6
#define KK 31
#define PADW 15
#define TP (TT + 2*PADW)      /* 2590 */
#define KPAD 640
#define NROW (BB*TT)          /* 20480 */
#define BNEPS 1e-5f

// ---- scratch (device globals: allocation-free) ----
// planar NCHW: plane c is [BB][T][F]
__device__ float g_buf1[(long)C1*BB*TT*FF];   // conv1 out, planar
__device__ float g_buf2[(long)C1*BB*TT*F2];   // conv2+pool out, planar
__device__ float g_buf3[(long)NROW*FEAT];     // conv3+pool out (c*57+f) per row
__device__ float g_Wc[144*KPAD];              // fused fc+qkv weights (48 q | 48 k | 48 v) x 627 (padded)
__device__ float g_bc[144];
__device__ float g_q[(long)NROW*MCC];
__device__ float g_k[(long)BB*TP*MCC];        // padded along T
__device__ float g_v[(long)BB*TP*MCC];

// ------------------------------------------------------------------
// conv1: 1->5 ch, 3x3 SAME, BN, ReLU -> planar out
// ------------------------------------------------------------------
__global__ void k_conv1(const float* __restrict__ spec, const float* __restrict__ w,
                        const float* __restrict__ cb, const float* __restrict__ bg,
                        const float* __restrict__ bb, const float* __restrict__ bm,
                        const float* __restrict__ bv) {
    __shared__ float ws[C1*9];
    __shared__ float sA[C1], sD[C1];
    int tid = threadIdx.x;
    if (tid < C1*9) ws[tid] = w[tid];
    if (tid < C1) {
        float s = bg[tid] * rsqrtf(bv[tid] + BNEPS);
        sA[tid] = s;
        sD[tid] = (cb[tid] - bm[tid]) * s + bb[tid];
    }
    __syncthreads();
    long idx = (long)blockIdx.x * blockDim.x + tid;
    if (idx >= (long)BB*TT*FF) return;
    int f = (int)(idx % FF);
    int t = (int)((idx / FF) % TT);
    int b = (int)(idx / ((long)FF*TT));
    float p[3][3];
#pragma unroll
    for (int ky = 0; ky < 3; ky++) {
        int tt2 = t - 1 + ky;
#pragma unroll
        for (int kx = 0; kx < 3; kx++) {
            int ff = f - 1 + kx;
            float val = 0.f;
            if (tt2 >= 0 && tt2 < TT && ff >= 0 && ff < FF)
                val = spec[((long)b*TT + tt2)*FF + ff];
            p[ky][kx] = val;
        }
    }
#pragma unroll
    for (int c = 0; c < C1; c++) {
        float acc = 0.f;
#pragma unroll
        for (int ky = 0; ky < 3; ky++)
#pragma unroll
            for (int kx = 0; kx < 3; kx++)
                acc = fmaf(ws[c*9 + ky*3 + kx], p[ky][kx], acc);
        g_buf1[(long)c*BB*TT*FF + idx] = fmaxf(fmaf(acc, sA[c], sD[c]), 0.f);
    }
}

// ------------------------------------------------------------------
// conv2: 5->5 ch, 3x3 SAME, BN, ReLU, maxpool W (229->114), planar in/out
// ------------------------------------------------------------------
__global__ void k_conv2(const float* __restrict__ w, const float* __restrict__ cb,
                        const float* __restrict__ bg, const float* __restrict__ bb,
                        const float* __restrict__ bm, const float* __restrict__ bv) {
    __shared__ float ws[C1*C1*9];
    __shared__ float sA[C1], sD[C1];
    int tid = threadIdx.x;
    for (int i = tid; i < C1*C1*9; i += blockDim.x) ws[i] = w[i];
    if (tid < C1) {
        float s = bg[tid] * rsqrtf(bv[tid] + BNEPS);
        sA[tid] = s;
        sD[tid] = (cb[tid] - bm[tid]) * s + bb[tid];
    }
    __syncthreads();
    long idx = (long)blockIdx.x * blockDim.x + tid;
    if (idx >= (long)BB*TT*F2) return;
    int f2 = (int)(idx % F2);
    int t  = (int)((idx / F2) % TT);
    int b  = (int)(idx / ((long)F2*TT));
    float acc[2][C1];
#pragma unroll
    for (int p = 0; p < 2; p++)
#pragma unroll
        for (int c = 0; c < C1; c++) acc[p][c] = 0.f;

#pragma unroll
    for (int ky = 0; ky < 3; ky++) {
        int tt2 = t - 1 + ky;
        if (tt2 < 0 || tt2 >= TT) continue;
#pragma unroll
        for (int ci = 0; ci < C1; ci++) {
            const float* plane = &g_buf1[((long)ci*BB*TT + (long)b*TT + tt2)*FF];
            float in4[4];
#pragma unroll
            for (int cx = 0; cx < 4; cx++) {
                int ff = 2*f2 - 1 + cx;
                in4[cx] = (ff >= 0 && ff < FF) ? plane[ff] : 0.f;
            }
#pragma unroll
            for (int co = 0; co < C1; co++) {
                const float* wr = &ws[((co*C1+ci)*3+ky)*3];
                acc[0][co] = fmaf(in4[0], wr[0], acc[0][co]);
                acc[0][co] = fmaf(in4[1], wr[1], acc[0][co]);
                acc[0][co] = fmaf(in4[2], wr[2], acc[0][co]);
                acc[1][co] = fmaf(in4[1], wr[0], acc[1][co]);
                acc[1][co] = fmaf(in4[2], wr[1], acc[1][co]);
                acc[1][co] = fmaf(in4[3], wr[2], acc[1][co]);
            }
        }
    }
#pragma unroll
    for (int co = 0; co < C1; co++) {
        float y0 = fmaxf(fmaf(acc[0][co], sA[co], sD[co]), 0.f);
        float y1 = fmaxf(fmaf(acc[1][co], sA[co], sD[co]), 0.f);
        g_buf2[(long)co*BB*TT*F2 + idx] = fmaxf(y0, y1);
    }
}

// ------------------------------------------------------------------
// conv3: 5->11 ch, 3x3 SAME, BN, ReLU, maxpool W (114->57)
// planar in, per-row feature out (c*57+f)
// ------------------------------------------------------------------
__global__ void k_conv3(const float* __restrict__ w, const float* __restrict__ cb,
                        const float* __restrict__ bg, const float* __restrict__ bb,
                        const float* __restrict__ bm, const float* __restrict__ bv) {
    __shared__ float ws[C2*C1*9];
    __shared__ float sA[C2], sD[C2];
    int tid = threadIdx.x;
    for (int i = tid; i < C2*C1*9; i += blockDim.x) ws[i] = w[i];
    if (tid < C2) {
        float s = bg[tid] * rsqrtf(bv[tid] + BNEPS);
        sA[tid] = s;
        sD[tid] = (cb[tid] - bm[tid]) * s + bb[tid];
    }
    __syncthreads();
    long idx = (long)blockIdx.x * blockDim.x + tid;
    if (idx >= (long)BB*TT*F3) return;
    int f2 = (int)(idx % F3);
    int t  = (int)((idx / F3) % TT);
    int b  = (int)(idx / ((long)F3*TT));
    float acc[2][C2];
#pragma unroll
    for (int p = 0; p < 2; p++)
#pragma unroll
        for (int c = 0; c < C2; c++) acc[p][c] = 0.f;

#pragma unroll
    for (int ky = 0; ky < 3; ky++) {
        int tt2 = t - 1 + ky;
        if (tt2 < 0 || tt2 >= TT) continue;
#pragma unroll
        for (int ci = 0; ci < C1; ci++) {
            const float* plane = &g_buf2[((long)ci*BB*TT + (long)b*TT + tt2)*F2];
            float in4[4];
#pragma unroll
            for (int cx = 0; cx < 4; cx++) {
                int ff = 2*f2 - 1 + cx;
                in4[cx] = (ff >= 0 && ff < F2) ? plane[ff] : 0.f;
            }
#pragma unroll
            for (int co = 0; co < C2; co++) {
                const float* wr = &ws[((co*C1+ci)*3+ky)*3];
                acc[0][co] = fmaf(in4[0], wr[0], acc[0][co]);
                acc[0][co] = fmaf(in4[1], wr[1], acc[0][co]);
                acc[0][co] = fmaf(in4[2], wr[2], acc[0][co]);
                acc[1][co] = fmaf(in4[1], wr[0], acc[1][co]);
                acc[1][co] = fmaf(in4[2], wr[1], acc[1][co]);
                acc[1][co] = fmaf(in4[3], wr[2], acc[1][co]);
            }
        }
    }
    float* o = &g_buf3[((long)b*TT + t) * FEAT];
#pragma unroll
    for (int co = 0; co < C2; co++) {
        float y0 = fmaxf(fmaf(acc[0][co], sA[co], sD[co]), 0.f);
        float y1 = fmaxf(fmaf(acc[1][co], sA[co], sD[co]), 0.f);
        o[co*F3 + f2] = fmaxf(y0, y1);
    }
}

// ------------------------------------------------------------------
// fold fc into q/k/v (g_Wc[r*KPAD + k], r = sec*48 + col)
// ------------------------------------------------------------------
__global__ void k_combine(const float* __restrict__ wq, const float* __restrict__ wk,
                          const float* __restrict__ wv, const float* __restrict__ fcw,
                          const float* __restrict__ fcb) {
    int idx = blockIdx.x * blockDim.x + threadIdx.x;
    if (idx >= 144*KPAD) return;
    int r = idx / KPAD, k = idx % KPAD;
    const float* wsel = (r < 48) ? (wq + r*OFT) : (r < 96) ? (wk + (r-48)*OFT) : (wv + (r-96)*OFT);
    float acc = 0.f;
    if (k < FEAT) {
        for (int m = 0; m < OFT; m++) acc = fmaf(wsel[m], fcw[(long)m*FEAT + k], acc);
    }
    g_Wc[idx] = acc;
    if (k == 0) {
        float bacc = 0.f;
        for (int m = 0; m < OFT; m++) bacc = fmaf(wsel[m], fcb[m], bacc);
        g_bc[r] = bacc;
    }
}

// zero the T-pad rows of k/v
__global__ void k_padzero() {
    int idx = blockIdx.x * blockDim.x + threadIdx.x;
    int total = BB * 2*PADW * MCC;
    if (idx >= total) return;
    int c = idx % MCC;
    int r = (idx / MCC) % (2*PADW);
    int b = idx / (MCC * 2*PADW);
    int tp = (r < PADW) ? r : (TT + PADW + (r - PADW));
    g_k[((long)b*TP + tp)*MCC + c] = 0.f;
    g_v[((long)b*TP + tp)*MCC + c] = 0.f;
}

// ------------------------------------------------------------------
// QKV GEMM: 128x48 tile, 256 threads, 4x6 microtile, B transposed in smem
// ------------------------------------------------------------------
__global__ void __launch_bounds__(256) k_qkv() {
    __shared__ float Xs[128][33];
    __shared__ float Ws[32][50];
    int tid = threadIdx.x;
    int sec = blockIdx.y;
    int row0 = blockIdx.x * 128;
    int tx = tid & 7;      // col group: cols [tx*6, tx*6+6)
    int ty = tid >> 3;     // row group: rows [ty*4, ty*4+4)

    float bias[6];
#pragma unroll
    for (int j = 0; j < 6; j++) bias[j] = g_bc[sec*48 + tx*6 + j];

    float acc[4][6];
#pragma unroll
    for (int i = 0; i < 4; i++)
#pragma unroll
        for (int j = 0; j < 6; j++) acc[i][j] = 0.f;

    for (int k0 = 0; k0 < KPAD; k0 += 32) {
#pragma unroll
        for (int i = 0; i < 16; i++) {
            int e = tid + 256*i;
            int r = e >> 5, c = e & 31;
            int kk = k0 + c;
            Xs[r][c] = (kk < FEAT) ? g_buf3[(long)(row0 + r)*FEAT + kk] : 0.f;
        }
#pragma unroll
        for (int i = 0; i < 6; i++) {
            int e = tid + 256*i;
            int r = e >> 5, c = e & 31;
            Ws[c][r] = g_Wc[(long)(sec*48 + r)*KPAD + k0 + c];
        }
        __syncthreads();

#pragma unroll
        for (int kk = 0; kk < 32; kk++) {
            float2 b01 = *(const float2*)&Ws[kk][tx*6];
            float2 b23 = *(const float2*)&Ws[kk][tx*6 + 2];
            float2 b45 = *(const float2*)&Ws[kk][tx*6 + 4];
            float bv[6] = {b01.x, b01.y, b23.x, b23.y, b45.x, b45.y};
#pragma unroll
            for (int i = 0; i < 4; i++) {
                float a = Xs[ty*4 + i][kk];
#pragma unroll
                for (int j = 0; j < 6; j++)
                    acc[i][j] = fmaf(a, bv[j], acc[i][j]);
            }
        }
        __syncthreads();
    }

#pragma unroll
    for (int i = 0; i < 4; i++) {
        int row = row0 + ty*4 + i;
        int b = row / TT, t = row % TT;
        float2 v0 = make_float2(acc[i][0] + bias[0], acc[i][1] + bias[1]);
        float2 v1 = make_float2(acc[i][2] + bias[2], acc[i][3] + bias[3]);
        float2 v2 = make_float2(acc[i][4] + bias[4], acc[i][5] + bias[5]);
        if (sec == 0) {
            float* dst = &g_q[(long)row*MCC + tx*6];
            *(float2*)(dst)     = v0;
            *(float2*)(dst + 2) = v1;
            *(float2*)(dst + 4) = v2;
        } else {
            float* base = (sec == 1) ? g_k : g_v;
            float* dst = &base[((long)b*TP + t + PADW)*MCC + tx*6];
            *(float2*)(dst)     = v0;
            *(float2*)(dst + 2) = v1;
            *(float2*)(dst + 4) = v2;
        }
    }
}

// ------------------------------------------------------------------
// fused attention + LN + linear + sigmoid; one warp per (b,t)
// K and V windows staged in smem (38 contiguous rows per block)
// ------------------------------------------------------------------
__global__ void k_attn(const float* __restrict__ rel, const float* __restrict__ lng,
                       const float* __restrict__ lnb, const float* __restrict__ linw,
                       const float* __restrict__ linb, float* __restrict__ out) {
    __shared__ __align__(16) float s_rel[MCC*KK];
    __shared__ __align__(16) float s_linw[OFT*MCC];
    __shared__ __align__(16) float s_linb[OFT];
    __shared__ __align__(16) float s_lng[MCC], s_lnb[MCC];
    __shared__ __align__(16) float s_q[8][MCC];
    __shared__ __align__(16) float s_k[38][49];   // stride 49: conflict-free row-varying reads
    __shared__ __align__(16) float s_v[38][48];   // float4 stores: base 16B-aligned, rows 48*4B
    __shared__ __align__(16) float s_attn[8][GG][KK+1];
    __shared__ __align__(16) float s_h[8][MCC];
    int tid = threadIdx.x;
    for (int i = tid; i < MCC*KK; i += 256) s_rel[i] = rel[i];
    for (int i = tid; i < OFT*MCC; i += 256) s_linw[i] = linw[i];
    if (tid < OFT) s_linb[tid] = linb[tid];
    if (tid < MCC) { s_lng[tid] = lng[tid]; s_lnb[tid] = lnb[tid]; }

    int bt0 = blockIdx.x * 8;
    int b = bt0 / TT, t0 = bt0 % TT;    // blocks never straddle batches (TT % 8 == 0)

    // stage K/V: 38 rows x 48 = contiguous region starting at (b*TP + t0)*48
    {
        const float4* ksrc = (const float4*)&g_k[((long)b*TP + t0)*MCC];
        const float4* vsrc = (const float4*)&g_v[((long)b*TP + t0)*MCC];
        for (int i = tid; i < 38*12; i += 256) {
            int r = i / 12, c4 = i % 12;
            float4 kq = ksrc[i];
            int cc = c4*4;
            s_k[r][cc] = kq.x; s_k[r][cc+1] = kq.y; s_k[r][cc+2] = kq.z; s_k[r][cc+3] = kq.w;
            *(float4*)&s_v[r][cc] = vsrc[i];
        }
    }
    __syncthreads();

    int wid = tid >> 5, lane = tid & 31;
    int bt = bt0 + wid;

    s_q[wid][lane] = g_q[(long)bt*MCC + lane];
    if (lane < 16) s_q[wid][lane + 32] = g_q[(long)bt*MCC + lane + 32];
    __syncwarp();

    int j = lane;
    float e[GG];
    if (j < KK) {
        const float* kr = &s_k[wid + j][0];
#pragma unroll
        for (int g = 0; g < GG; g++) {
            float s = 0.f;
#pragma unroll
            for (int d = 0; d < DH; d++) {
                int c = g*DH + d;
                s = fmaf(s_q[wid][c], kr[c] + s_rel[c*KK + j], s);
            }
            e[g] = s;
        }
    } else {
#pragma unroll
        for (int g = 0; g < GG; g++) e[g] = -INFINITY;
    }

    long aoff = (long)NROW*OFT + (long)bt*GG*KK;
#pragma unroll
    for (int g = 0; g < GG; g++) {
        float m = e[g];
#pragma unroll
        for (int o = 16; o; o >>= 1) m = fmaxf(m, __shfl_xor_sync(0xffffffffu, m, o));
        float p = (j < KK) ? __expf(e[g] - m) : 0.f;
        float s = p;
#pragma unroll
        for (int o = 16; o; o >>= 1) s += __shfl_xor_sync(0xffffffffu, s, o);
        float a = p / s;
        if (j < KK) {
            s_attn[wid][g][j] = a;
            out[aoff + g*KK + j] = a;
        }
    }
    __syncwarp();

    int c1 = lane;
    int c2 = lane + 32;
    int g1 = c1 / DH;
    int g2 = c2 / DH;
    float o1 = 0.f, o2 = 0.f;
#pragma unroll
    for (int jj = 0; jj < KK; jj++) {
        const float* vr = &s_v[wid + jj][0];
        o1 = fmaf(s_attn[wid][g1][jj], vr[c1], o1);
        if (lane < 16)
            o2 = fmaf(s_attn[wid][g2][jj], vr[c2], o2);
    }

    float lsum = o1 + ((lane < 16) ? o2 : 0.f);
    float lsq  = o1*o1 + ((lane < 16) ? o2*o2 : 0.f);
#pragma unroll
    for (int o = 16; o; o >>= 1) {
        lsum += __shfl_xor_sync(0xffffffffu, lsum, o);
        lsq  += __shfl_xor_sync(0xffffffffu, lsq,  o);
    }
    float mu = lsum * (1.f/48.f);
    float var = lsq * (1.f/48.f) - mu*mu;
    float inv = rsqrtf(var + 1e-5f);
    s_h[wid][c1] = (o1 - mu)*inv*s_lng[c1] + s_lnb[c1];
    if (lane < 16) s_h[wid][c2] = (o2 - mu)*inv*s_lng[c2] + s_lnb[c2];
    __syncwarp();

#pragma unroll
    for (int rr = 0; rr < 3; rr++) {
        int o = lane + rr*32;
        if (o < OFT) {
            float s = s_linb[o];
#pragma unroll
            for (int c = 0; c < MCC; c++)
                s = fmaf(s_h[wid][c], s_linw[o*MCC + c], s);
            out[(long)bt*OFT + o] = 1.f / (1.f + __expf(-s));
        }
    }
}

// ------------------------------------------------------------------
extern "C" void kernel_launch(void* const* d_in, const int* in_sizes, int n_in,
                              void* d_out, int out_size) {
    const float* spec = (const float*)d_in[0];
    const float* c1w  = (const float*)d_in[1];
    const float* c1b  = (const float*)d_in[2];
    const float* bn1g = (const float*)d_in[3];
    const float* bn1b = (const float*)d_in[4];
    const float* bn1m = (const float*)d_in[5];
    const float* bn1v = (const float*)d_in[6];
    const float* c2w  = (const float*)d_in[7];
    const float* c2b  = (const float*)d_in[8];
    const float* bn2g = (const float*)d_in[9];
    const float* bn2b = (const float*)d_in[10];
    const float* bn2m = (const float*)d_in[11];
    const float* bn2v = (const float*)d_in[12];
    const float* c3w  = (const float*)d_in[13];
    const float* c3b  = (const float*)d_in[14];
    const float* bn3g = (const float*)d_in[15];
    const float* bn3b = (const float*)d_in[16];
    const float* bn3m = (const float*)d_in[17];
    const float* bn3v = (const float*)d_in[18];
    const float* fcw  = (const float*)d_in[19];
    const float* fcb  = (const float*)d_in[20];
    const float* wq   = (const float*)d_in[21];
    const float* wk   = (const float*)d_in[22];
    const float* wv   = (const float*)d_in[23];
    const float* rel  = (const float*)d_in[24];
    const float* lng  = (const float*)d_in[25];
    const float* lnb  = (const float*)d_in[26];
    const float* linw = (const float*)d_in[27];
    const float* linb = (const float*)d_in[28];
    float* out = (float*)d_out;

    k_conv1<<<(BB*TT*FF + 255)/256, 256>>>(spec, c1w, c1b, bn1g, bn1b, bn1m, bn1v);
    k_conv2<<<(BB*TT*F2 + 255)/256, 256>>>(c2w, c2b, bn2g, bn2b, bn2m, bn2v);
    k_conv3<<<(BB*TT*F3 + 255)/256, 256>>>(c3w, c3b, bn3g, bn3b, bn3m, bn3v);
    k_combine<<<(144*KPAD + 255)/256, 256>>>(wq, wk, wv, fcw, fcb);
    k_padzero<<<(BB*2*PADW*MCC + 255)/256, 256>>>();
    {
        dim3 grid(NROW/128, 3);
        k_qkv<<<grid, 256>>>();
    }
    k_attn<<<NROW/8, 256>>>(rel, lng, lnb, linw, linb, out);
}